// round 9
// baseline (speedup 1.0000x reference)
#include <cuda_runtime.h>
#include <cstdint>
#include <cstddef>

// ---------------------------------------------------------------------------
// ReLU-LSTM: S=2048, B=128, H=256, IN=256, L=2; one (h,c) state threads
// through both layers and time.
//
//   prologue_kernel: P[t,b,:] = x_t @ w_ih0^T + b_ih0 + b_hh0 (parallel),
//                    2-way k-split, stored P[row][ht*64 + r], r = g*16 + hv.
//   lstm_kernel:     persistent 128-CTA x 256-thread kernel; 4096 phases.
//                    Warps = 4 k-quarters x 2 batch-halves; thread owns
//                    8 batch rows x 2 gate-rows. Layer1 W = w_ih1 + w_hh1.
//
// R9: k-quarter remap (crossbar 3072->2048 cyc/phase), epilogue-only
// warp-level barrier arrivals, per-warp acquire polls, prologue k-split.
// ---------------------------------------------------------------------------

#define S_    2048
#define B_    128
#define H_    256
#define IN_   256
#define GH_   1024
#define NCTA  128         // 8 bt x 16 ht
#define NTHR  256
#define PNTHR 128
#define WPAD  260

#define OUT_Y  ((size_t)S_ * B_ * H_)
#define HY_OFF (OUT_Y)
#define CY_OFF (OUT_Y + 2ull * B_ * H_)

typedef unsigned long long ull;

__device__ float    g_P[(size_t)S_ * B_ * GH_];
__device__ float    g_hbuf[2][B_ * H_];
__device__ unsigned g_bars[8][64];                   // per-bt ctr, 256B stride

__device__ __forceinline__ float sigf(float x) {
  float e = __expf(-x);
  float d = 1.0f + e;
  float r;
  asm("rcp.approx.f32 %0, %1;" : "=f"(r) : "f"(d));
  return r;
}

__device__ __forceinline__ void ffma2(ull& acc, ull a, ull w) {
  asm("fma.rn.f32x2 %0, %1, %2, %0;" : "+l"(acc) : "l"(a), "l"(w));
}
__device__ __forceinline__ ull pack1(float lo) {
  ull r; asm("mov.b64 %0, {%1, %2};" : "=l"(r) : "f"(lo), "f"(0.0f));
  return r;
}
__device__ __forceinline__ float unpack_sum(ull v) {
  float lo, hi;
  asm("mov.b64 {%0, %1}, %2;" : "=f"(lo), "=f"(hi) : "l"(v));
  return lo + hi;
}

// ---------------------------------------------------------------------------
// Prologue: grid (16 ht, 1024 blocks of 256 rows), 128 threads, 2 CTA/SM.
// Warps = 2 k-halves x 2 batch-halves; thread = 8 rows x 2 gate-rows.
// ---------------------------------------------------------------------------
__global__ void __launch_bounds__(PNTHR) prologue_kernel(
    const float* __restrict__ x,    const float* __restrict__ h0,
    const float* __restrict__ w_ih, const float* __restrict__ b_ih,
    const float* __restrict__ b_hh) {
  extern __shared__ float sm[];
  float* sW = sm;               // 64 x WPAD
  float* sA = sm + 64 * WPAD;   // 16 x WPAD
  float* sR = sm + 80 * WPAD;   // 16 x 64 partials (k-half 1)
  const int tid = threadIdx.x;
  const int ht  = blockIdx.x;

  if (blockIdx.y == 0) {
    if (blockIdx.x == 0 && tid < 8) g_bars[tid][0] = 0u;
    for (int i = blockIdx.x * PNTHR + tid; i < B_ * H_; i += 16 * PNTHR)
      g_hbuf[0][i] = h0[i];
  }

  for (int idx = tid; idx < 64 * 64; idx += PNTHR) {
    int r = idx >> 6, kq4 = idx & 63;
    int g = r >> 4, hv2 = r & 15;
    int gcol = g * 256 + ht * 16 + hv2;
    *(float4*)&sW[r * WPAD + kq4 * 4] =
        __ldg((const float4*)(w_ih + (size_t)gcol * IN_) + kq4);
  }
  const int hl  = tid & 31;
  const int wid = tid >> 5;          // 0..3
  const int kh  = wid & 1;
  const int bh  = wid >> 1;
  const int kb  = kh * 128;
  float bias[2];
#pragma unroll
  for (int gi = 0; gi < 2; ++gi) {
    int r = hl + gi * 32;
    int gcol = (r >> 4) * 256 + ht * 16 + (r & 15);
    bias[gi] = b_ih[gcol] + b_hh[gcol];
  }
  const float* wp = sW + hl * WPAD;
  const float* wq = wp + 32 * WPAD;
  const float* aB = sA + (bh * 8) * WPAD;

  for (int sub = 0; sub < 16; ++sub) {
    size_t rows0 = (size_t)blockIdx.y * 256 + sub * 16;
    __syncthreads();   // weights ready (sub 0) / prior sA+sR readers done
    for (int idx = tid; idx < 16 * 64; idx += PNTHR) {
      int rr = idx >> 6, kq4 = idx & 63;
      *(float4*)&sA[rr * WPAD + kq4 * 4] =
          __ldg((const float4*)(x + (rows0 + rr) * IN_) + kq4);
    }
    __syncthreads();
    ull acc[8][2];
#pragma unroll
    for (int j = 0; j < 8; ++j) {
      acc[j][0] = (kh == 0) ? pack1(bias[0]) : 0ull;
      acc[j][1] = (kh == 0) ? pack1(bias[1]) : 0ull;
    }
#pragma unroll 8
    for (int k4 = 0; k4 < 128; k4 += 4) {
      int k = kb + k4;
      ulonglong2 w0 = *(const ulonglong2*)(wp + k);
      ulonglong2 w1 = *(const ulonglong2*)(wq + k);
#pragma unroll
      for (int j = 0; j < 8; ++j) {
        ulonglong2 a = *(const ulonglong2*)(aB + j * WPAD + k);
        ffma2(acc[j][0], a.x, w0.x); ffma2(acc[j][0], a.y, w0.y);
        ffma2(acc[j][1], a.x, w1.x); ffma2(acc[j][1], a.y, w1.y);
      }
    }
    if (kh == 1) {
#pragma unroll
      for (int j = 0; j < 8; ++j) {
        sR[(bh * 8 + j) * 64 + hl]      = unpack_sum(acc[j][0]);
        sR[(bh * 8 + j) * 64 + 32 + hl] = unpack_sum(acc[j][1]);
      }
    }
    __syncthreads();
    if (kh == 0) {
#pragma unroll
      for (int j = 0; j < 8; ++j) {
        size_t row = rows0 + bh * 8 + j;
        size_t base = row * GH_ + ht * 64;
        int rb = (bh * 8 + j) * 64;
        __stcs(&g_P[base + hl],      unpack_sum(acc[j][0]) + sR[rb + hl]);
        __stcs(&g_P[base + 32 + hl], unpack_sum(acc[j][1]) + sR[rb + 32 + hl]);
      }
    }
  }
}

// Per-warp acquire poll (lane 0 polls; syncwarp propagates ordering).
__device__ __forceinline__ void bar_wait_warp(unsigned* ctr, unsigned target) {
  if ((threadIdx.x & 31) == 0) {
    unsigned v;
    do {
      asm volatile("ld.acquire.gpu.b32 %0, [%1];" : "=r"(v) : "l"(ctr) : "memory");
    } while (v < target);
  }
  __syncwarp();
}

// ---------------------------------------------------------------------------
// Persistent recurrent kernel: 128 CTAs (8 bt x 16 ht) x 256 threads.
// wid = tid>>5: kq = wid&3 (k-quarter), bh = wid>>2 (batch half).
// Thread: 8 batch rows (bh*8+j), gate-rows hl & hl+32, k in [kq*64, +64).
// kq==0 warps own epilogue + c-state (hl>=16 lanes) + barrier arrivals.
// ---------------------------------------------------------------------------
__global__ void __launch_bounds__(NTHR, 1) lstm_kernel(
    const float* __restrict__ c0,
    const float* __restrict__ w_ih, const float* __restrict__ b_ih,
    const float* __restrict__ w_hh, const float* __restrict__ b_hh,
    float* __restrict__ out) {
  extern __shared__ float sm[];
  float* sW0 = sm;               // 64 x WPAD
  float* sW1 = sm + 64 * WPAD;   // 64 x WPAD
  float* sA  = sm + 128 * WPAD;  // 16 x WPAD
  float* sR  = sm + 144 * WPAD;  // 16 x 192 partials (kq 1..3)
  const int tid = threadIdx.x;
  const int bt  = blockIdx.x >> 4;
  const int ht  = blockIdx.x & 15;
  const int hl  = tid & 31;
  const int wid = tid >> 5;
  const int kq  = wid & 3;
  const int bh  = wid >> 2;
  const int kb  = kq * 64;
  const int hv  = hl & 15;
  const bool epi = (kq == 0);
  const bool isB = (hl >= 16);
  const int hglob = ht * 16 + hv;
  unsigned* ctr = &g_bars[bt][0];

  // Resident weights: rows r = g*16 + hv.
  for (int idx = tid; idx < 64 * 64; idx += NTHR) {
    int r = idx >> 6, kq4 = idx & 63;
    int g = r >> 4, hv2 = r & 15;
    int gcol = g * 256 + ht * 16 + hv2;
    *(float4*)&sW0[r * WPAD + kq4 * 4] =
        __ldg((const float4*)(w_hh + (size_t)gcol * H_) + kq4);
    float4 wa = __ldg((const float4*)(w_ih + (size_t)(GH_ + gcol) * IN_) + kq4);
    float4 wb = __ldg((const float4*)(w_hh + (size_t)(GH_ + gcol) * H_) + kq4);
    *(float4*)&sW1[r * WPAD + kq4 * 4] =
        make_float4(wa.x + wb.x, wa.y + wb.y, wa.z + wb.z, wa.w + wb.w);
  }
  float bias1[2];
#pragma unroll
  for (int gi = 0; gi < 2; ++gi) {
    int r = hl + gi * 32;
    int gcol = (r >> 4) * 256 + ht * 16 + (r & 15);
    bias1[gi] = b_ih[GH_ + gcol] + b_hh[GH_ + gcol];
  }
  const float* wp0 = sW0 + hl * WPAD;
  const float* wq0 = wp0 + 32 * WPAD;
  const float* wp1 = sW1 + hl * WPAD;
  const float* wq1 = wp1 + 32 * WPAD;
  const float* aB  = sA + (bh * 8) * WPAD;

  float c[8];
  float pr[8][2];
  if (epi) {
#pragma unroll
    for (int j = 0; j < 8; ++j) {
      int b = bt * 16 + bh * 8 + j;
      if (isB) c[j] = c0[(size_t)b * H_ + hglob];
      size_t base = (size_t)b * GH_ + ht * 64;
      pr[j][0] = __ldcs(&g_P[base + hl]);
      pr[j][1] = __ldcs(&g_P[base + 32 + hl]);
    }
  }

  unsigned target = 0;

  for (int t = 0; t < S_; ++t) {
#pragma unroll 1
    for (int phase = 0; phase < 2; ++phase) {
      if (target) bar_wait_warp(ctr, target);
      // ---- stage h tile (per-warp slices, one CTA sync before GEMM) ----
      const float* hsrc = g_hbuf[phase];
      for (int idx = tid; idx < 16 * 64; idx += NTHR) {
        int rr = idx >> 6, kq4 = idx & 63;
        *(float4*)&sA[rr * WPAD + kq4 * 4] =
            __ldcg((const float4*)&hsrc[(size_t)(bt * 16 + rr) * H_] + kq4);
      }
      __syncthreads();
      // ---- GEMM (k-quarter slices) ----
      ull acc[8][2];
      if (epi) {
        if (phase == 0) {
#pragma unroll
          for (int j = 0; j < 8; ++j) {
            acc[j][0] = pack1(pr[j][0]); acc[j][1] = pack1(pr[j][1]);
          }
        } else {
#pragma unroll
          for (int j = 0; j < 8; ++j) {
            acc[j][0] = pack1(bias1[0]); acc[j][1] = pack1(bias1[1]);
          }
        }
      } else {
#pragma unroll
        for (int j = 0; j < 8; ++j) { acc[j][0] = 0ull; acc[j][1] = 0ull; }
      }
      const float* wp = phase ? wp1 : wp0;
      const float* wq = phase ? wq1 : wq0;
#pragma unroll
      for (int k4 = 0; k4 < 64; k4 += 4) {
        int k = kb + k4;
        ulonglong2 w0 = *(const ulonglong2*)(wp + k);
        ulonglong2 w1 = *(const ulonglong2*)(wq + k);
#pragma unroll
        for (int j = 0; j < 8; ++j) {
          ulonglong2 a = *(const ulonglong2*)(aB + j * WPAD + k);
          ffma2(acc[j][0], a.x, w0.x); ffma2(acc[j][0], a.y, w0.y);
          ffma2(acc[j][1], a.x, w1.x); ffma2(acc[j][1], a.y, w1.y);
        }
      }
      if (!epi) {
#pragma unroll
        for (int j = 0; j < 8; ++j) {
          int rb = (bh * 8 + j) * 192 + (kq - 1) * 64;
          sR[rb + hl]      = unpack_sum(acc[j][0]);
          sR[rb + 32 + hl] = unpack_sum(acc[j][1]);
        }
      }
      __syncthreads();
      // ---- epilogue (kq==0 warps only) ----
      if (epi) {
        float hout[8];
#pragma unroll
        for (int j = 0; j < 8; ++j) {
          int bl = bh * 8 + j;
          int b  = bt * 16 + bl;
          int rb = bl * 192;
          float g0 = unpack_sum(acc[j][0]) + sR[rb + hl] + sR[rb + 64 + hl] +
                     sR[rb + 128 + hl];
          float g1 = unpack_sum(acc[j][1]) + sR[rb + 32 + hl] +
                     sR[rb + 96 + hl] + sR[rb + 160 + hl];
          // hl<16: g0=ig, g1=cg.  hl>=16: g0=fg, g1=og.
          float s0 = sigf(g0);
          float u  = s0 * fmaxf(g1, 0.0f);
          float uin = __shfl_xor_sync(0xFFFFFFFFu, u, 16);
          if (isB) {
            c[j] = s0 * c[j] + uin;
            float h = sigf(g1) * fmaxf(c[j], 0.0f);
            hout[j] = h;
            __stcg(&g_hbuf[phase ^ 1][(size_t)b * H_ + hglob], h);
            if (t == S_ - 1) {
              size_t lo = (size_t)phase * B_ * H_ + (size_t)b * H_ + hglob;
              out[HY_OFF + lo] = h;
              out[CY_OFF + lo] = c[j];
            }
          }
        }
        __syncwarp();
        if (hl == 0)
          asm volatile("red.release.gpu.global.add.u32 [%0], %1;"
                       :: "l"(ctr), "r"(1u) : "memory");
        // Overlap window (inside barrier skew): out stores + P prefetch.
        if (phase == 1) {
          if (isB) {
#pragma unroll
            for (int j = 0; j < 8; ++j) {
              int b = bt * 16 + bh * 8 + j;
              __stcs(&out[(size_t)t * B_ * H_ + (size_t)b * H_ + hglob], hout[j]);
            }
          }
          if (t + 1 < S_) {
#pragma unroll
            for (int j = 0; j < 8; ++j) {
              int b = bt * 16 + bh * 8 + j;
              size_t base = ((size_t)(t + 1) * B_ + b) * GH_ + ht * 64;
              pr[j][0] = __ldcs(&g_P[base + hl]);
              pr[j][1] = __ldcs(&g_P[base + 32 + hl]);
            }
          }
        }
      }
      target += 32;   // 2 epilogue-warp arrivals x 16 CTAs per phase
    }
  }
}

extern "C" void kernel_launch(void* const* d_in, const int* in_sizes, int n_in,
                              void* d_out, int out_size) {
  const float* x    = (const float*)d_in[0];
  const float* h0   = (const float*)d_in[1];
  const float* c0   = (const float*)d_in[2];
  const float* w_ih = (const float*)d_in[3];
  const float* b_ih = (const float*)d_in[4];
  const float* w_hh = (const float*)d_in[5];
  const float* b_hh = (const float*)d_in[6];
  float* out = (float*)d_out;

  const int PRO_SMEM  = (80 * WPAD + 1024) * sizeof(float);   //  87,296 B
  const int LSTM_SMEM = (144 * WPAD + 3072) * sizeof(float);  // 162,048 B
  static bool attr_done = false;
  if (!attr_done) {
    cudaFuncSetAttribute(prologue_kernel,
                         cudaFuncAttributeMaxDynamicSharedMemorySize, PRO_SMEM);
    cudaFuncSetAttribute(lstm_kernel,
                         cudaFuncAttributeMaxDynamicSharedMemorySize, LSTM_SMEM);
    attr_done = true;
  }

  dim3 pgrid(16, (S_ * B_) / 256);
  prologue_kernel<<<pgrid, PNTHR, PRO_SMEM>>>(x, h0, w_ih, b_ih, b_hh);
  lstm_kernel<<<NCTA, NTHR, LSTM_SMEM>>>(c0, w_ih, b_ih, w_hh, b_hh, out);
}

// round 12
// speedup vs baseline: 2.2524x; 2.2524x over previous
#include <cuda_runtime.h>
#include <cuda_bf16.h>
#include <cstdint>
#include <cstddef>

// ---------------------------------------------------------------------------
// ReLU-LSTM: S=2048, B=128, H=256, IN=256, L=2; one (h,c) state threads
// through both layers and time.
//
//  prologue_kernel: P[t,b,:] = x_t @ w_ih0^T + b_ih0 + b_hh0 (all t parallel),
//      stored column-permuted col' = ht*64 + hv*4 + g so the lstm epilogue
//      reads one float4 per cell. Also copies h0 -> g_hbuf[0], resets bars.
//  lstm_kernel: persistent 128-CTA (8 bt x 16 ht) x 256-thread kernel.
//      Per phase: 16x64x256 GEMM via mma.sync m16n8k16 bf16 (split-bf16,
//      3 products: ah*wh + ah*wl + al*wh), fp32 accum. Weights resident in
//      SMEM as bf16 hi/lo tiles; h staged fp32->bf16 hi/lo per phase.
//      Layer1 W = w_ih1 + w_hh1. c-state: 1 register per thread (1 cell).
// ---------------------------------------------------------------------------

#define S_    2048
#define B_    128
#define H_    256
#define IN_   256
#define GH_   1024
#define NCTA  128
#define NTHR  256
#define PNTHR 128
#define WPAD  260

#define OUT_Y  ((size_t)S_ * B_ * H_)
#define HY_OFF (OUT_Y)
#define CY_OFF (OUT_Y + 2ull * B_ * H_)

// SMEM byte offsets (lstm kernel)
#define APITCH_B 528                    // 264 bf16 per row
#define OFF_ALO  8448                   // 16 x 528
#define OFF_W    16896
#define WTILE_B  33792                  // 64 x 528
#define OFF_D    (OFF_W + 4 * WTILE_B)  // 152064
#define LSTM_SMEM (OFF_D + 16 * 68 * 4) // 156416 B

typedef unsigned long long ull;

__device__ float    g_P[(size_t)S_ * B_ * GH_];
__device__ float    g_hbuf[2][B_ * H_];
__device__ unsigned g_bars[8][64];      // per-bt ctr, 256B stride

__device__ __forceinline__ float sigf(float x) {
  float e = __expf(-x);
  float d = 1.0f + e;
  float r;
  asm("rcp.approx.f32 %0, %1;" : "=f"(r) : "f"(d));
  return r;
}
__device__ __forceinline__ void ffma2(ull& acc, ull a, ull w) {
  asm("fma.rn.f32x2 %0, %1, %2, %0;" : "+l"(acc) : "l"(a), "l"(w));
}
__device__ __forceinline__ ull pack1(float lo) {
  ull r; asm("mov.b64 %0, {%1, %2};" : "=l"(r) : "f"(lo), "f"(0.0f));
  return r;
}
__device__ __forceinline__ float unpack_sum(ull v) {
  float lo, hi;
  asm("mov.b64 {%0, %1}, %2;" : "=f"(lo), "=f"(hi) : "l"(v));
  return lo + hi;
}
__device__ __forceinline__ uint32_t s2u(const void* p) {
  uint32_t a;
  asm("{ .reg .u64 t; cvta.to.shared.u64 t, %1; cvt.u32.u64 %0, t; }"
      : "=r"(a) : "l"(p));
  return a;
}

#define LDSM_X4(r0, r1, r2, r3, addr)                                      \
  asm volatile("ldmatrix.sync.aligned.m8n8.x4.shared.b16 {%0,%1,%2,%3}, [%4];" \
               : "=r"(r0), "=r"(r1), "=r"(r2), "=r"(r3) : "r"(addr))

#define MMA_BF16(d, a0, a1, a2, a3, b0, b1)                                \
  asm volatile("mma.sync.aligned.m16n8k16.row.col.f32.bf16.bf16.f32 "      \
               "{%0,%1,%2,%3}, {%4,%5,%6,%7}, {%8,%9}, {%0,%1,%2,%3};"     \
               : "+f"(d[0]), "+f"(d[1]), "+f"(d[2]), "+f"(d[3])            \
               : "r"(a0), "r"(a1), "r"(a2), "r"(a3), "r"(b0), "r"(b1))

// ---------------------------------------------------------------------------
// Prologue: grid (16 ht, 1024 blocks of 256 rows), 128 threads.
// ---------------------------------------------------------------------------
__global__ void __launch_bounds__(PNTHR) prologue_kernel(
    const float* __restrict__ x,    const float* __restrict__ h0,
    const float* __restrict__ w_ih, const float* __restrict__ b_ih,
    const float* __restrict__ b_hh) {
  extern __shared__ float sm[];
  float* sW = sm;              // 64 x WPAD
  float* sA = sm + 64 * WPAD;  // 32 x WPAD
  const int tid = threadIdx.x;
  const int ht  = blockIdx.x;

  if (blockIdx.y == 0) {
    if (blockIdx.x == 0 && tid < 8) g_bars[tid][0] = 0u;
    for (int i = blockIdx.x * PNTHR + tid; i < B_ * H_; i += 16 * PNTHR)
      g_hbuf[0][i] = h0[i];
  }

  for (int idx = tid; idx < 64 * 64; idx += PNTHR) {
    int r = idx >> 6, kq4 = idx & 63;
    int g = r >> 4, hv = r & 15;
    int gcol = g * 256 + ht * 16 + hv;
    *(float4*)&sW[r * WPAD + kq4 * 4] =
        __ldg((const float4*)(w_ih + (size_t)gcol * IN_) + kq4);
  }
  const int hl = tid & 31, bq = tid >> 5;
  float bias[2];
  int colp[2];
#pragma unroll
  for (int gi = 0; gi < 2; ++gi) {
    int r = hl + gi * 32;
    int g = r >> 4, hv = r & 15;
    int gcol = g * 256 + ht * 16 + hv;
    bias[gi] = b_ih[gcol] + b_hh[gcol];
    colp[gi] = hv * 4 + g;                 // hv-major, gate-minor
  }
  const float* w0p = sW + hl * WPAD;
  const float* w1p = sW + (hl + 32) * WPAD;
  const float* aB  = sA + (bq * 8) * WPAD;

  for (int sub = 0; sub < 8; ++sub) {
    size_t rows0 = (size_t)blockIdx.y * 256 + sub * 32;
    __syncthreads();
    for (int idx = tid; idx < 32 * 64; idx += PNTHR) {
      int rr = idx >> 6, kq4 = idx & 63;
      *(float4*)&sA[rr * WPAD + kq4 * 4] =
          __ldg((const float4*)(x + (rows0 + rr) * IN_) + kq4);
    }
    __syncthreads();
    ull acc[8][2];
#pragma unroll
    for (int j = 0; j < 8; ++j) {
      acc[j][0] = pack1(bias[0]); acc[j][1] = pack1(bias[1]);
    }
#pragma unroll 4
    for (int k = 0; k < 256; k += 4) {
      ulonglong2 w0 = *(const ulonglong2*)(w0p + k);
      ulonglong2 w1 = *(const ulonglong2*)(w1p + k);
#pragma unroll
      for (int j = 0; j < 8; ++j) {
        ulonglong2 a = *(const ulonglong2*)(aB + j * WPAD + k);
        ffma2(acc[j][0], a.x, w0.x); ffma2(acc[j][0], a.y, w0.y);
        ffma2(acc[j][1], a.x, w1.x); ffma2(acc[j][1], a.y, w1.y);
      }
    }
#pragma unroll
    for (int j = 0; j < 8; ++j) {
      size_t base = (rows0 + bq * 8 + j) * GH_ + ht * 64;
      __stcs(&g_P[base + colp[0]], unpack_sum(acc[j][0]));
      __stcs(&g_P[base + colp[1]], unpack_sum(acc[j][1]));
    }
  }
}

// Per-bt 16-CTA barrier (R8-validated form).
__device__ __forceinline__ void bar_arrive(unsigned* ctr) {
  __syncthreads();
  if (threadIdx.x == 0) {
    asm volatile("red.release.gpu.global.add.u32 [%0], %1;"
                 :: "l"(ctr), "r"(1u) : "memory");
  }
}
__device__ __forceinline__ void bar_wait(unsigned* ctr, unsigned target) {
  if (threadIdx.x == 0) {
    unsigned v;
    do {
      asm volatile("ld.acquire.gpu.b32 %0, [%1];" : "=r"(v) : "l"(ctr) : "memory");
    } while (v < target);
  }
  __syncthreads();
}

// ---------------------------------------------------------------------------
// Persistent recurrent kernel: 128 CTAs (8 bt x 16 ht) x 256 threads.
// Warp w: gate g = w&3, hv-half = w>>2. Thread tid: cell (b = tid>>4,
// hv = tid&15) for the epilogue; c-state in 1 register.
// ---------------------------------------------------------------------------
__global__ void __launch_bounds__(NTHR, 1) lstm_kernel(
    const float* __restrict__ c0,
    const float* __restrict__ w_ih, const float* __restrict__ b_ih,
    const float* __restrict__ w_hh, const float* __restrict__ b_hh,
    float* __restrict__ out) {
  extern __shared__ char smemc[];
  __nv_bfloat16* sWq = (__nv_bfloat16*)(smemc + OFF_W);
  float*         sD  = (float*)(smemc + OFF_D);      // 16 x 68 fp32
  const uint32_t sbase = s2u(smemc);

  const int tid  = threadIdx.x;
  const int lane = tid & 31;
  const int wid  = tid >> 5;
  const int bt   = blockIdx.x >> 4;
  const int ht   = blockIdx.x & 15;
  const int g    = wid & 3;
  const int half = wid >> 2;
  unsigned* ctr = &g_bars[bt][0];

  // ---- stage resident weights (once): rows r = g*16 + hv, 264-elem pitch --
  for (int idx = tid; idx < 64 * 256; idx += NTHR) {
    int r = idx >> 8, k = idx & 255;
    int gg = r >> 4, hv2 = r & 15;
    int gc = gg * 256 + ht * 16 + hv2;
    float v0 = w_hh[(size_t)gc * H_ + k];
    __nv_bfloat16 h0b = __float2bfloat16(v0);
    sWq[0 * 16896 + r * 264 + k] = h0b;
    sWq[1 * 16896 + r * 264 + k] = __float2bfloat16(v0 - __bfloat162float(h0b));
    float v1 = w_ih[(size_t)(GH_ + gc) * IN_ + k] + w_hh[(size_t)(GH_ + gc) * H_ + k];
    __nv_bfloat16 h1b = __float2bfloat16(v1);
    sWq[2 * 16896 + r * 264 + k] = h1b;
    sWq[3 * 16896 + r * 264 + k] = __float2bfloat16(v1 - __bfloat162float(h1b));
  }

  const int brow  = tid >> 4;          // 0..15
  const int hv    = tid & 15;
  const int bglob = bt * 16 + brow;
  const int hglob = ht * 16 + hv;
  float bias4[4];
#pragma unroll
  for (int gg = 0; gg < 4; ++gg) {
    int gc = gg * 256 + ht * 16 + hv;
    bias4[gg] = b_ih[GH_ + gc] + b_hh[GH_ + gc];
  }
  float cst = c0[(size_t)bglob * H_ + hglob];
  float4 pv = __ldcs((const float4*)&g_P[(size_t)bglob * GH_ + ht * 64 + hv * 4]);

  // ldmatrix base addresses
  const uint32_t aHiAddr = sbase + (lane & 15) * APITCH_B + ((lane >> 4) & 1) * 16;
  const uint32_t aLoAddr = aHiAddr + OFF_ALO;
  const uint32_t bRowOff = (uint32_t)((g * 16 + half * 8 + (lane & 7)) * APITCH_B +
                                      ((lane >> 3) & 3) * 16);

  unsigned target = 16;

  for (int t = 0; t < S_; ++t) {
#pragma unroll 1
    for (int ph = 0; ph < 2; ++ph) {
      // ---- stage A: fp32 h -> bf16 hi/lo SMEM tiles ----
      {
        const float* hr = &g_hbuf[ph][(size_t)bglob * H_ + hv * 16];
        uint32_t hi[8], lo[8];
#pragma unroll
        for (int qq = 0; qq < 4; ++qq) {
          float4 v = __ldcg((const float4*)hr + qq);
          float f[4] = {v.x, v.y, v.z, v.w};
#pragma unroll
          for (int pp = 0; pp < 2; ++pp) {
            __nv_bfloat16 hA = __float2bfloat16(f[pp * 2]);
            __nv_bfloat16 hB = __float2bfloat16(f[pp * 2 + 1]);
            __nv_bfloat16 lA = __float2bfloat16(f[pp * 2] - __bfloat162float(hA));
            __nv_bfloat16 lB = __float2bfloat16(f[pp * 2 + 1] - __bfloat162float(hB));
            hi[qq * 2 + pp] = (uint32_t)__bfloat16_as_ushort(hA) |
                              ((uint32_t)__bfloat16_as_ushort(hB) << 16);
            lo[qq * 2 + pp] = (uint32_t)__bfloat16_as_ushort(lA) |
                              ((uint32_t)__bfloat16_as_ushort(lB) << 16);
          }
        }
        uint32_t doff = (uint32_t)(brow * APITCH_B + hv * 32);
        *(uint4*)(smemc + doff)            = make_uint4(hi[0], hi[1], hi[2], hi[3]);
        *(uint4*)(smemc + doff + 16)       = make_uint4(hi[4], hi[5], hi[6], hi[7]);
        *(uint4*)(smemc + OFF_ALO + doff)      = make_uint4(lo[0], lo[1], lo[2], lo[3]);
        *(uint4*)(smemc + OFF_ALO + doff + 16) = make_uint4(lo[4], lo[5], lo[6], lo[7]);
      }
      __syncthreads();

      // ---- GEMM: 48 HMMA per warp (split-bf16, 3 products) ----
      float d[4] = {0.f, 0.f, 0.f, 0.f};
      {
        const uint32_t wBase = sbase + OFF_W + (ph ? 2u * WTILE_B : 0u);
        const uint32_t bHi = wBase + bRowOff;
        const uint32_t bLo = bHi + WTILE_B;
#pragma unroll
        for (int kp = 0; kp < 8; ++kp) {
          uint32_t ah0, ah1, ah2, ah3, ah4, ah5, ah6, ah7;
          uint32_t al0, al1, al2, al3, al4, al5, al6, al7;
          uint32_t bh0, bh1, bh2, bh3, bl0, bl1, bl2, bl3;
          LDSM_X4(ah0, ah1, ah2, ah3, aHiAddr + kp * 64);
          LDSM_X4(ah4, ah5, ah6, ah7, aHiAddr + kp * 64 + 32);
          LDSM_X4(al0, al1, al2, al3, aLoAddr + kp * 64);
          LDSM_X4(al4, al5, al6, al7, aLoAddr + kp * 64 + 32);
          LDSM_X4(bh0, bh1, bh2, bh3, bHi + kp * 64);
          LDSM_X4(bl0, bl1, bl2, bl3, bLo + kp * 64);
          MMA_BF16(d, ah0, ah1, ah2, ah3, bh0, bh1);
          MMA_BF16(d, ah0, ah1, ah2, ah3, bl0, bl1);
          MMA_BF16(d, al0, al1, al2, al3, bh0, bh1);
          MMA_BF16(d, ah4, ah5, ah6, ah7, bh2, bh3);
          MMA_BF16(d, ah4, ah5, ah6, ah7, bl2, bl3);
          MMA_BF16(d, al4, al5, al6, al7, bh2, bh3);
        }
      }
      // ---- D -> SMEM (col index = hv*4 + gate) ----
      {
        int r0 = lane >> 2;
        int c0i = half * 8 + (lane & 3) * 2;
        sD[r0 * 68 + c0i * 4 + g]        = d[0];
        sD[r0 * 68 + (c0i + 1) * 4 + g]  = d[1];
        sD[(r0 + 8) * 68 + c0i * 4 + g]       = d[2];
        sD[(r0 + 8) * 68 + (c0i + 1) * 4 + g] = d[3];
      }
      __syncthreads();

      // ---- cell epilogue: 1 thread = 1 (b, hv) cell ----
      float4 dv = *(const float4*)&sD[brow * 68 + hv * 4];
      float ai, af, ac, ao;
      if (ph) { ai = bias4[0]; af = bias4[1]; ac = bias4[2]; ao = bias4[3]; }
      else    { ai = pv.x;     af = pv.y;     ac = pv.z;     ao = pv.w;     }
      float ig = dv.x + ai, fg = dv.y + af, cg = dv.z + ac, og = dv.w + ao;
      cst = sigf(fg) * cst + sigf(ig) * fmaxf(cg, 0.0f);
      float h = sigf(og) * fmaxf(cst, 0.0f);
      __stcg(&g_hbuf[ph ^ 1][(size_t)bglob * H_ + hglob], h);
      if (t == S_ - 1) {
        size_t lo2 = (size_t)ph * B_ * H_ + (size_t)bglob * H_ + hglob;
        out[HY_OFF + lo2] = h;
        out[CY_OFF + lo2] = cst;
      }
      bar_arrive(ctr);
      // Overlap window: out stores + next-step P prefetch.
      if (ph) {
        __stcs(&out[(size_t)t * B_ * H_ + (size_t)bglob * H_ + hglob], h);
        if (t + 1 < S_)
          pv = __ldcs((const float4*)
                      &g_P[((size_t)(t + 1) * B_ + bglob) * GH_ + ht * 64 + hv * 4]);
      }
      bar_wait(ctr, target); target += 16;
    }
  }
}

extern "C" void kernel_launch(void* const* d_in, const int* in_sizes, int n_in,
                              void* d_out, int out_size) {
  const float* x    = (const float*)d_in[0];
  const float* h0   = (const float*)d_in[1];
  const float* c0   = (const float*)d_in[2];
  const float* w_ih = (const float*)d_in[3];
  const float* b_ih = (const float*)d_in[4];
  const float* w_hh = (const float*)d_in[5];
  const float* b_hh = (const float*)d_in[6];
  float* out = (float*)d_out;

  const int PRO_SMEM = 96 * WPAD * sizeof(float);   // 99,840 B
  static bool attr_done = false;
  if (!attr_done) {
    cudaFuncSetAttribute(prologue_kernel,
                         cudaFuncAttributeMaxDynamicSharedMemorySize, PRO_SMEM);
    cudaFuncSetAttribute(lstm_kernel,
                         cudaFuncAttributeMaxDynamicSharedMemorySize, LSTM_SMEM);
    attr_done = true;
  }

  dim3 pgrid(16, (S_ * B_) / 256);
  prologue_kernel<<<pgrid, PNTHR, PRO_SMEM>>>(x, h0, w_ih, b_ih, b_hh);
  lstm_kernel<<<NCTA, NTHR, LSTM_SMEM>>>(c0, w_ih, b_ih, w_hh, b_hh, out);
}

// round 13
// speedup vs baseline: 2.5870x; 1.1486x over previous
#include <cuda_runtime.h>
#include <cuda_bf16.h>
#include <cstdint>
#include <cstddef>

// ---------------------------------------------------------------------------
// ReLU-LSTM: S=2048, B=128, H=256, IN=256, L=2; one (h,c) state threads
// through both layers and time.
//
//  prologue_kernel: P[t,b,:] = x_t @ w_ih0^T + b_ih0 + b_hh0 (all t parallel),
//      columns permuted col' = ht*64 + hv*4 + g. Writes h0 as split-bf16 into
//      g_img[0]; resets barriers.
//  lstm_kernel: persistent 128-CTA (8 bt x 16 ht) x 512-thread kernel.
//      2 layer-dedicated warp groups x 8 warps. Per phase the active group
//      computes D[16,64] = A[16,256] x W[64,256]^T via mma.sync m16n8k16
//      split-bf16 (ah*wh + ah*wl + al*wh). W fragments live in REGISTERS
//      (loaded once). h circulates as per-bt global bf16 hi/lo images in the
//      exact (swizzled) SMEM A layout; staging is cp.async. Epilogue is in
//      registers via one shfl.xor; c-state in SMEM. Layer1 W = w_ih1 + w_hh1.
// ---------------------------------------------------------------------------

#define S_    2048
#define B_    128
#define H_    256
#define IN_   256
#define GH_   1024
#define NCTA  128
#define NTHR  512
#define PNTHR 128
#define WPAD  260

#define OUT_Y  ((size_t)S_ * B_ * H_)
#define HY_OFF (OUT_Y)
#define CY_OFF (OUT_Y + 2ull * B_ * H_)

// lstm SMEM map (bytes)
#define OFF_A    0          // A tile: hi 8192 + lo 8192
#define OFF_WST  16384      // W staging (64 rows x 512B)
#define OFF_C    49152      // c-state: 16x17+ floats
#define LSTM_SMEM 50688

typedef unsigned long long ull;

__device__ float g_P[(size_t)S_ * B_ * GH_];
__device__ __align__(16) unsigned char g_img[2][8][2][8192];  // [buf][bt][hi|lo]
__device__ unsigned g_bars[8][64];

__device__ __forceinline__ float sigf(float x) {
  float e = __expf(-x);
  float d = 1.0f + e;
  float r;
  asm("rcp.approx.f32 %0, %1;" : "=f"(r) : "f"(d));
  return r;
}
__device__ __forceinline__ void ffma2(ull& acc, ull a, ull w) {
  asm("fma.rn.f32x2 %0, %1, %2, %0;" : "+l"(acc) : "l"(a), "l"(w));
}
__device__ __forceinline__ ull pack1(float lo) {
  ull r; asm("mov.b64 %0, {%1, %2};" : "=l"(r) : "f"(lo), "f"(0.0f));
  return r;
}
__device__ __forceinline__ float unpack_sum(ull v) {
  float lo, hi;
  asm("mov.b64 {%0, %1}, %2;" : "=f"(lo), "=f"(hi) : "l"(v));
  return lo + hi;
}
__device__ __forceinline__ uint32_t s2u(const void* p) {
  uint32_t a;
  asm("{ .reg .u64 t; cvta.to.shared.u64 t, %1; cvt.u32.u64 %0, t; }"
      : "=r"(a) : "l"(p));
  return a;
}

// 16B-chunk XOR swizzle within 128B groups: chunk c of row r.
__device__ __forceinline__ int swz(int r, int c) {
  return (c & 24) | ((c ^ r) & 7);
}

#define LDSM_X4(r0, r1, r2, r3, addr)                                          \
  asm volatile("ldmatrix.sync.aligned.m8n8.x4.shared.b16 {%0,%1,%2,%3}, [%4];" \
               : "=r"(r0), "=r"(r1), "=r"(r2), "=r"(r3) : "r"(addr))

#define MMA_BF16(d, a0, a1, a2, a3, b0, b1)                                \
  asm volatile("mma.sync.aligned.m16n8k16.row.col.f32.bf16.bf16.f32 "      \
               "{%0,%1,%2,%3}, {%4,%5,%6,%7}, {%8,%9}, {%0,%1,%2,%3};"     \
               : "+f"(d[0]), "+f"(d[1]), "+f"(d[2]), "+f"(d[3])            \
               : "r"(a0), "r"(a1), "r"(a2), "r"(a3), "r"(b0), "r"(b1))

#define CP_ASYNC16(dst, src)                                               \
  asm volatile("cp.async.ca.shared.global [%0], [%1], 16;"                 \
               :: "r"(dst), "l"(src) : "memory")

// ---------------------------------------------------------------------------
// Prologue: grid (16 ht, 1024 blocks of 256 rows), 128 threads. (R12 GEMM.)
// ---------------------------------------------------------------------------
__global__ void __launch_bounds__(PNTHR) prologue_kernel(
    const float* __restrict__ x,    const float* __restrict__ h0,
    const float* __restrict__ w_ih, const float* __restrict__ b_ih,
    const float* __restrict__ b_hh) {
  extern __shared__ float sm[];
  float* sW = sm;              // 64 x WPAD
  float* sA = sm + 64 * WPAD;  // 32 x WPAD
  const int tid = threadIdx.x;
  const int ht  = blockIdx.x;

  if (blockIdx.y == 0) {
    if (blockIdx.x == 0 && tid < 8) g_bars[tid][0] = 0u;
    // h0 -> split-bf16 image 0 (per-bt plain row layout; swizzle is only in SMEM)
    for (int i = blockIdx.x * PNTHR + tid; i < B_ * H_; i += 16 * PNTHR) {
      int b = i >> 8, h = i & 255;
      float v = h0[i];
      __nv_bfloat16 hb = __float2bfloat16(v);
      __nv_bfloat16 lb = __float2bfloat16(v - __bfloat162float(hb));
      *(__nv_bfloat16*)&g_img[0][b >> 4][0][(b & 15) * 512 + h * 2] = hb;
      *(__nv_bfloat16*)&g_img[0][b >> 4][1][(b & 15) * 512 + h * 2] = lb;
    }
  }

  for (int idx = tid; idx < 64 * 64; idx += PNTHR) {
    int r = idx >> 6, kq4 = idx & 63;
    int g = r >> 4, hv = r & 15;
    int gcol = g * 256 + ht * 16 + hv;
    *(float4*)&sW[r * WPAD + kq4 * 4] =
        __ldg((const float4*)(w_ih + (size_t)gcol * IN_) + kq4);
  }
  const int hl = tid & 31, bq = tid >> 5;
  float bias[2];
  int colp[2];
#pragma unroll
  for (int gi = 0; gi < 2; ++gi) {
    int r = hl + gi * 32;
    int g = r >> 4, hv = r & 15;
    int gcol = g * 256 + ht * 16 + hv;
    bias[gi] = b_ih[gcol] + b_hh[gcol];
    colp[gi] = hv * 4 + g;
  }
  const float* w0p = sW + hl * WPAD;
  const float* w1p = sW + (hl + 32) * WPAD;
  const float* aB  = sA + (bq * 8) * WPAD;

  for (int sub = 0; sub < 8; ++sub) {
    size_t rows0 = (size_t)blockIdx.y * 256 + sub * 32;
    __syncthreads();
    for (int idx = tid; idx < 32 * 64; idx += PNTHR) {
      int rr = idx >> 6, kq4 = idx & 63;
      *(float4*)&sA[rr * WPAD + kq4 * 4] =
          __ldg((const float4*)(x + (rows0 + rr) * IN_) + kq4);
    }
    __syncthreads();
    ull acc[8][2];
#pragma unroll
    for (int j = 0; j < 8; ++j) {
      acc[j][0] = pack1(bias[0]); acc[j][1] = pack1(bias[1]);
    }
#pragma unroll 4
    for (int k = 0; k < 256; k += 4) {
      ulonglong2 w0 = *(const ulonglong2*)(w0p + k);
      ulonglong2 w1 = *(const ulonglong2*)(w1p + k);
#pragma unroll
      for (int j = 0; j < 8; ++j) {
        ulonglong2 a = *(const ulonglong2*)(aB + j * WPAD + k);
        ffma2(acc[j][0], a.x, w0.x); ffma2(acc[j][0], a.y, w0.y);
        ffma2(acc[j][1], a.x, w1.x); ffma2(acc[j][1], a.y, w1.y);
      }
    }
#pragma unroll
    for (int j = 0; j < 8; ++j) {
      size_t base = (rows0 + bq * 8 + j) * GH_ + ht * 64;
      __stcs(&g_P[base + colp[0]], unpack_sum(acc[j][0]));
      __stcs(&g_P[base + colp[1]], unpack_sum(acc[j][1]));
    }
  }
}

__device__ __forceinline__ void bar_arrive(unsigned* ctr) {
  __syncthreads();
  if (threadIdx.x == 0) {
    asm volatile("red.release.gpu.global.add.u32 [%0], %1;"
                 :: "l"(ctr), "r"(1u) : "memory");
  }
}
__device__ __forceinline__ void bar_wait(unsigned* ctr, unsigned target) {
  if (threadIdx.x == 0) {
    unsigned v;
    do {
      asm volatile("ld.acquire.gpu.b32 %0, [%1];" : "=r"(v) : "l"(ctr) : "memory");
    } while (v < target);
  }
  __syncthreads();
}

// ---------------------------------------------------------------------------
// Persistent recurrent kernel: 128 CTAs (8 bt x 16 ht) x 512 threads.
// Warp w: grp = w>>3 (layer), nsl = w&7 (n-slice: cols [nsl*8, nsl*8+8)).
// ---------------------------------------------------------------------------
__global__ void __launch_bounds__(NTHR, 1) lstm_kernel(
    const float* __restrict__ c0,
    const float* __restrict__ w_ih, const float* __restrict__ b_ih,
    const float* __restrict__ w_hh, const float* __restrict__ b_hh,
    float* __restrict__ out) {
  extern __shared__ char smemc[];
  float* sC = (float*)(smemc + OFF_C);
  const uint32_t sbase = s2u(smemc);

  const int tid  = threadIdx.x;
  const int lane = tid & 31;
  const int wid  = tid >> 5;
  const int bt   = blockIdx.x >> 4;
  const int ht   = blockIdx.x & 15;
  const int grp  = wid >> 3;      // 0: layer0 warps, 1: layer1 warps
  const int nsl  = wid & 7;       // n-slice
  unsigned* ctr  = &g_bars[bt][0];

  // ---- stage W -> registers (4 passes: layer x plane) ----
  uint32_t bH[8][4], bL[8][4];
  {
    const int rrow = nsl * 8 + (lane & 7);
    const int bsel = (lane >> 3) & 3;
#pragma unroll 1
    for (int l = 0; l < 2; ++l) {
#pragma unroll 1
      for (int p = 0; p < 2; ++p) {
        for (int idx = tid; idx < 64 * 256; idx += NTHR) {
          int n = idx >> 8, k = idx & 255;
          int g = n & 3, hv = n >> 2;
          int gcol = g * 256 + ht * 16 + hv;
          float v;
          if (l == 0) v = w_hh[(size_t)gcol * H_ + k];
          else v = w_ih[(size_t)(GH_ + gcol) * IN_ + k] +
                   w_hh[(size_t)(GH_ + gcol) * H_ + k];
          __nv_bfloat16 hb = __float2bfloat16(v);
          __nv_bfloat16 sv = p == 0 ? hb
                           : __float2bfloat16(v - __bfloat162float(hb));
          int c = k >> 3;
          *(__nv_bfloat16*)(smemc + OFF_WST + n * 512 + swz(n, c) * 16 +
                            (k & 7) * 2) = sv;
        }
        __syncthreads();
        if (grp == l) {
#pragma unroll
          for (int kp = 0; kp < 8; ++kp) {
            int c = kp * 4 + bsel;
            uint32_t addr = sbase + OFF_WST + rrow * 512 + swz(rrow, c) * 16;
            if (p == 0) { LDSM_X4(bH[kp][0], bH[kp][1], bH[kp][2], bH[kp][3], addr); }
            else        { LDSM_X4(bL[kp][0], bL[kp][1], bL[kp][2], bL[kp][3], addr); }
          }
        }
        __syncthreads();
      }
    }
  }

  // ---- cell / lane mapping ----
  const int hv_c   = nsl * 2 + ((lane & 3) >> 1);
  const int bl_c   = (lane >> 2) + ((lane & 1) ? 8 : 0);
  const int bglob  = bt * 16 + bl_c;
  const int hglob  = ht * 16 + hv_c;
  float4 bias4 = make_float4(0.f, 0.f, 0.f, 0.f);
  if (grp == 1) {
#pragma unroll
    for (int g = 0; g < 4; ++g) {
      int gc = g * 256 + ht * 16 + hv_c;
      ((float*)&bias4)[g] = b_ih[GH_ + gc] + b_hh[GH_ + gc];
    }
  }
  // c-state init (pitch 17)
  if (tid < 256) sC[(tid >> 4) * 17 + (tid & 15)] =
      c0[(size_t)(bt * 16 + (tid >> 4)) * H_ + ht * 16 + (tid & 15)];
  __syncthreads();

  float4 pv = make_float4(0.f, 0.f, 0.f, 0.f);
  if (grp == 0)
    pv = __ldcs((const float4*)&g_P[(size_t)bglob * GH_ + ht * 64 + hv_c * 4]);

  // A-tile ldmatrix lane addressing
  const int rA = lane & 15, eA = lane >> 4;
  const uint32_t aRow = sbase + OFF_A + rA * 512;

#pragma unroll 1
  for (int q = 0; q < 2 * S_; ++q) {
    const int t  = q >> 1;
    const int ph = q & 1;
    if (q) bar_wait(ctr, (unsigned)q * 16);

    // ---- stage A: cp.async from g_img[ph][bt] into swizzled SMEM ----
    {
      int i0 = tid;           // chunk ids: tid, tid+512  (1024 chunks)
#pragma unroll
      for (int ii = 0; ii < 2; ++ii) {
        int idx = i0 + ii * NTHR;
        int p = idx >> 9, rem = idx & 511;
        int r = rem >> 5, c = rem & 31;
        uint32_t dst = sbase + OFF_A + p * 8192 + r * 512 + swz(r, c) * 16;
        const unsigned char* src = &g_img[ph][bt][p][r * 512 + c * 16];
        CP_ASYNC16(dst, src);
      }
      asm volatile("cp.async.commit_group;" ::: "memory");
      asm volatile("cp.async.wait_group 0;" ::: "memory");
    }
    __syncthreads();

    if (grp == ph) {
      // ---- GEMM: 48 HMMA, A via LDSM, B from registers ----
      float d[4] = {0.f, 0.f, 0.f, 0.f};
#pragma unroll
      for (int kp = 0; kp < 8; ++kp) {
        uint32_t h0r, h1r, h2r, h3r, h4, h5, h6, h7;
        uint32_t l0, l1, l2, l3, l4, l5, l6, l7;
        int c0c = 4 * kp + eA;       // ktile 2kp
        int c1c = 4 * kp + 2 + eA;   // ktile 2kp+1
        uint32_t a0 = aRow + swz(rA, c0c) * 16;
        uint32_t a1 = aRow + swz(rA, c1c) * 16;
        LDSM_X4(h0r, h1r, h2r, h3r, a0);
        LDSM_X4(l0, l1, l2, l3, a0 + 8192);
        LDSM_X4(h4, h5, h6, h7, a1);
        LDSM_X4(l4, l5, l6, l7, a1 + 8192);
        MMA_BF16(d, h0r, h1r, h2r, h3r, bH[kp][0], bH[kp][1]);
        MMA_BF16(d, h0r, h1r, h2r, h3r, bL[kp][0], bL[kp][1]);
        MMA_BF16(d, l0, l1, l2, l3,     bH[kp][0], bH[kp][1]);
        MMA_BF16(d, h4, h5, h6, h7,     bH[kp][2], bH[kp][3]);
        MMA_BF16(d, h4, h5, h6, h7,     bL[kp][2], bL[kp][3]);
        MMA_BF16(d, l4, l5, l6, l7,     bH[kp][2], bH[kp][3]);
      }
      // ---- register epilogue: shfl pairs (i,f) with (c,o) ----
      float e0 = __shfl_xor_sync(0xFFFFFFFFu, d[0], 1);
      float e1 = __shfl_xor_sync(0xFFFFFFFFu, d[1], 1);
      float e2 = __shfl_xor_sync(0xFFFFFFFFu, d[2], 1);
      float e3 = __shfl_xor_sync(0xFFFFFFFFu, d[3], 1);
      float gi, gf, gc, go;
      if (!(lane & 1)) { gi = d[0]; gf = d[1]; gc = e0; go = e1; }
      else             { gi = e2;   gf = e3;   gc = d[2]; go = d[3]; }
      float4 ab = (grp == 0) ? pv : bias4;
      gi += ab.x; gf += ab.y; gc += ab.z; go += ab.w;
      int ci = bl_c * 17 + hv_c;
      float cold = sC[ci];
      float cnew = sigf(gf) * cold + sigf(gi) * fmaxf(gc, 0.0f);
      float h = sigf(go) * fmaxf(cnew, 0.0f);
      sC[ci] = cnew;
      __nv_bfloat16 hb = __float2bfloat16(h);
      __nv_bfloat16 lb = __float2bfloat16(h - __bfloat162float(hb));
      *(__nv_bfloat16*)&g_img[ph ^ 1][bt][0][bl_c * 512 + hglob * 2] = hb;
      *(__nv_bfloat16*)&g_img[ph ^ 1][bt][1][bl_c * 512 + hglob * 2] = lb;
      if (t == S_ - 1) {
        size_t lo2 = (size_t)ph * B_ * H_ + (size_t)bglob * H_ + hglob;
        out[HY_OFF + lo2] = h;
        out[CY_OFF + lo2] = cnew;
      }
      bar_arrive(ctr);
      if (ph) __stcs(&out[(size_t)t * B_ * H_ + (size_t)bglob * H_ + hglob], h);
    } else {
      bar_arrive(ctr);
      // layer-0 warps prefetch next-step P during layer-1 phases
      if (grp == 0 && ph == 1 && t + 1 < S_)
        pv = __ldcs((const float4*)
                    &g_P[((size_t)(t + 1) * B_ + bglob) * GH_ + ht * 64 + hv_c * 4]);
    }
  }
}

extern "C" void kernel_launch(void* const* d_in, const int* in_sizes, int n_in,
                              void* d_out, int out_size) {
  const float* x    = (const float*)d_in[0];
  const float* h0   = (const float*)d_in[1];
  const float* c0   = (const float*)d_in[2];
  const float* w_ih = (const float*)d_in[3];
  const float* b_ih = (const float*)d_in[4];
  const float* w_hh = (const float*)d_in[5];
  const float* b_hh = (const float*)d_in[6];
  float* out = (float*)d_out;

  const int PRO_SMEM = 96 * WPAD * sizeof(float);   // 99,840 B
  static bool attr_done = false;
  if (!attr_done) {
    cudaFuncSetAttribute(prologue_kernel,
                         cudaFuncAttributeMaxDynamicSharedMemorySize, PRO_SMEM);
    cudaFuncSetAttribute(lstm_kernel,
                         cudaFuncAttributeMaxDynamicSharedMemorySize, LSTM_SMEM);
    attr_done = true;
  }

  dim3 pgrid(16, (S_ * B_) / 256);
  prologue_kernel<<<pgrid, PNTHR, PRO_SMEM>>>(x, h0, w_ih, b_ih, b_hh);
  lstm_kernel<<<NCTA, NTHR, LSTM_SMEM>>>(c0, w_ih, b_ih, w_hh, b_hh, out);
}

// round 15
// speedup vs baseline: 3.2505x; 1.2565x over previous
#include <cuda_runtime.h>
#include <cuda_bf16.h>
#include <cstdint>
#include <cstddef>

// ---------------------------------------------------------------------------
// ReLU-LSTM: S=2048, B=128, H=256, IN=256, L=2; one (h,c) state threads
// through both layers and time.
//
//  setup_kernel:  W0 -> pre-swizzled bf16 hi/lo image, h0 -> g_img[0],
//                 barrier reset.
//  xconv_kernel:  x -> global bf16 hi/lo images (split-bf16).
//  pro_main:      persistent 144-CTA HMMA GEMM:
//                 P[t,b,:] = x_t @ w_ih0^T + b_ih0 + b_hh0, columns permuted
//                 col' = hv*4 + g (matches lstm epilogue reads). W in
//                 registers, A double-buffered via cp.async.
//  lstm_kernel:   UNCHANGED from R13 (persistent 128 CTA x 512 thr, HMMA
//                 split-bf16, W in registers, cp.async h staging).
// ---------------------------------------------------------------------------

#define S_    2048
#define B_    128
#define H_    256
#define IN_   256
#define GH_   1024
#define NCTA  128
#define NTHR  512

#define OUT_Y  ((size_t)S_ * B_ * H_)
#define HY_OFF (OUT_Y)
#define CY_OFF (OUT_Y + 2ull * B_ * H_)

// lstm SMEM map (bytes)
#define OFF_A    0          // A tile: hi 8192 + lo 8192
#define OFF_WST  16384      // W staging (64 rows x 512B)
#define OFF_C    49152      // c-state: 16x17+ floats
#define LSTM_SMEM 50688

// prologue SMEM: two A buffers of 64KB (hi 32K + lo 32K); W staged in buf1.
#define PBUF_B   65536
#define PRO_SMEM 131072

typedef unsigned long long ull;

__device__ float g_P[(size_t)S_ * B_ * GH_];
__device__ __align__(16) unsigned char g_img[2][8][2][8192];  // [buf][bt][hi|lo]
__device__ __align__(16) unsigned char g_w0[16][2][32768];    // [ht][hi|lo] swizzled
__device__ __nv_bfloat16 g_xhi[(size_t)S_ * B_ * IN_];
__device__ __nv_bfloat16 g_xlo[(size_t)S_ * B_ * IN_];
__device__ unsigned g_bars[8][64];

__device__ __forceinline__ float sigf(float x) {
  float e = __expf(-x);
  float d = 1.0f + e;
  float r;
  asm("rcp.approx.f32 %0, %1;" : "=f"(r) : "f"(d));
  return r;
}
__device__ __forceinline__ uint32_t s2u(const void* p) {
  uint32_t a;
  asm("{ .reg .u64 t; cvta.to.shared.u64 t, %1; cvt.u32.u64 %0, t; }"
      : "=r"(a) : "l"(p));
  return a;
}
// 16B-chunk XOR swizzle within 128B groups: chunk c of row r.
__device__ __forceinline__ int swz(int r, int c) {
  return (c & 24) | ((c ^ r) & 7);
}

#define LDSM_X4(r0, r1, r2, r3, addr)                                          \
  asm volatile("ldmatrix.sync.aligned.m8n8.x4.shared.b16 {%0,%1,%2,%3}, [%4];" \
               : "=r"(r0), "=r"(r1), "=r"(r2), "=r"(r3) : "r"(addr))

#define MMA_BF16(d, a0, a1, a2, a3, b0, b1)                                \
  asm volatile("mma.sync.aligned.m16n8k16.row.col.f32.bf16.bf16.f32 "      \
               "{%0,%1,%2,%3}, {%4,%5,%6,%7}, {%8,%9}, {%0,%1,%2,%3};"     \
               : "+f"(d[0]), "+f"(d[1]), "+f"(d[2]), "+f"(d[3])            \
               : "r"(a0), "r"(a1), "r"(a2), "r"(a3), "r"(b0), "r"(b1))

#define CP_ASYNC16(dst, src)                                               \
  asm volatile("cp.async.ca.shared.global [%0], [%1], 16;"                 \
               :: "r"(dst), "l"(src) : "memory")
#define CP_COMMIT() asm volatile("cp.async.commit_group;" ::: "memory")
#define CP_WAIT(N)  asm volatile("cp.async.wait_group %0;" :: "n"(N) : "memory")

// ---------------------------------------------------------------------------
// setup: W0 bf16 hi/lo swizzled image, h0 image, barrier reset.
// grid 64 x 256 threads.
// ---------------------------------------------------------------------------
__global__ void __launch_bounds__(256) setup_kernel(
    const float* __restrict__ h0, const float* __restrict__ w_ih) {
  int gtid = blockIdx.x * 256 + threadIdx.x;   // 16384 threads
  if (gtid < 8) g_bars[gtid][0] = 0u;
  for (int i = gtid; i < B_ * H_; i += 16384) {
    int b = i >> 8, h = i & 255;
    float v = h0[i];
    __nv_bfloat16 hb = __float2bfloat16(v);
    __nv_bfloat16 lb = __float2bfloat16(v - __bfloat162float(hb));
    *(__nv_bfloat16*)&g_img[0][b >> 4][0][(b & 15) * 512 + h * 2] = hb;
    *(__nv_bfloat16*)&g_img[0][b >> 4][1][(b & 15) * 512 + h * 2] = lb;
  }
  for (int widx = gtid; widx < 16 * 64 * 256; widx += 16384) {
    int ht = widx >> 14, n = (widx >> 8) & 63, k = widx & 255;
    int gcol = (n & 3) * 256 + ht * 16 + (n >> 2);
    float v = w_ih[(size_t)gcol * IN_ + k];
    __nv_bfloat16 hb = __float2bfloat16(v);
    __nv_bfloat16 lb = __float2bfloat16(v - __bfloat162float(hb));
    int off = n * 512 + swz(n, k >> 3) * 16 + (k & 7) * 2;
    *(__nv_bfloat16*)&g_w0[ht][0][off] = hb;
    *(__nv_bfloat16*)&g_w0[ht][1][off] = lb;
  }
}

// ---------------------------------------------------------------------------
// xconv: x fp32 -> bf16 hi/lo images. grid 16384 x 512 threads, 8 el/thread.
// ---------------------------------------------------------------------------
__global__ void __launch_bounds__(512) xconv_kernel(const float* __restrict__ x) {
  size_t base = ((size_t)blockIdx.x * 512 + threadIdx.x) * 8;
  float4 v0 = __ldcs((const float4*)(x + base));
  float4 v1 = __ldcs((const float4*)(x + base + 4));
  float f[8] = {v0.x, v0.y, v0.z, v0.w, v1.x, v1.y, v1.z, v1.w};
  uint32_t hi[4], lo[4];
#pragma unroll
  for (int i = 0; i < 4; ++i) {
    __nv_bfloat16 hA = __float2bfloat16(f[2 * i]);
    __nv_bfloat16 hB = __float2bfloat16(f[2 * i + 1]);
    __nv_bfloat16 lA = __float2bfloat16(f[2 * i] - __bfloat162float(hA));
    __nv_bfloat16 lB = __float2bfloat16(f[2 * i + 1] - __bfloat162float(hB));
    hi[i] = (uint32_t)__bfloat16_as_ushort(hA) |
            ((uint32_t)__bfloat16_as_ushort(hB) << 16);
    lo[i] = (uint32_t)__bfloat16_as_ushort(lA) |
            ((uint32_t)__bfloat16_as_ushort(lB) << 16);
  }
  __stcs((uint4*)&g_xhi[base], make_uint4(hi[0], hi[1], hi[2], hi[3]));
  __stcs((uint4*)&g_xlo[base], make_uint4(lo[0], lo[1], lo[2], lo[3]));
}

// ---------------------------------------------------------------------------
// pro_main: persistent HMMA prologue. grid (16 ht, 9) x 256 threads.
// Each CTA: W regs once; loops 64-row x-blocks (rb = yid, yid+9, ...).
// ---------------------------------------------------------------------------
__global__ void __launch_bounds__(256) pro_main(
    const float* __restrict__ b_ih, const float* __restrict__ b_hh) {
  extern __shared__ char psm[];
  const uint32_t sbase = s2u(psm);
  const int tid  = threadIdx.x;
  const int lane = tid & 31;
  const int wid  = tid >> 5;      // = n-slice (8 warps x 8 cols)
  const int ht   = blockIdx.x;
  const int yid  = blockIdx.y;

  // ---- issue W load (into buf1 region) + first A load (buf0) ----
#pragma unroll
  for (int i = 0; i < 16; ++i) {            // 4096 W chunks
    int idx = tid + i * 256;
    int p = idx >> 11, cid = idx & 2047;
    CP_ASYNC16(sbase + PBUF_B + p * 32768 + cid * 16, &g_w0[ht][p][cid * 16]);
  }
  CP_COMMIT();
  {
    int rb = yid;
#pragma unroll
    for (int i = 0; i < 16; ++i) {          // 4096 A chunks
      int idx = tid + i * 256;
      int p = idx >> 11, rem = idx & 2047;
      int r = rem >> 5, c = rem & 31;
      const __nv_bfloat16* xp = p ? g_xlo : g_xhi;
      CP_ASYNC16(sbase + p * 32768 + r * 512 + swz(r, c) * 16,
                 (const char*)xp + ((size_t)(rb * 64 + r)) * 512 + c * 16);
    }
    CP_COMMIT();
  }
  CP_WAIT(1);          // W arrived (A0 may be in flight)
  __syncthreads();

  // ---- W -> registers ----
  uint32_t bH[8][4], bL[8][4];
  {
    const int rrow = wid * 8 + (lane & 7);
    const int bsel = (lane >> 3) & 3;
#pragma unroll
    for (int kp = 0; kp < 8; ++kp) {
      uint32_t aH = sbase + PBUF_B + rrow * 512 + swz(rrow, kp * 4 + bsel) * 16;
      LDSM_X4(bH[kp][0], bH[kp][1], bH[kp][2], bH[kp][3], aH);
      LDSM_X4(bL[kp][0], bL[kp][1], bL[kp][2], bL[kp][3], aH + 32768);
    }
  }
  __syncthreads();     // W region free -> becomes A buf1

  // bias for this thread's two columns
  const int n0 = wid * 8 + (lane & 3) * 2;
  float bias0, bias1;
  {
    int gc0 = (n0 & 3) * 256 + ht * 16 + (n0 >> 2);
    int gc1 = ((n0 + 1) & 3) * 256 + ht * 16 + ((n0 + 1) >> 2);
    bias0 = b_ih[gc0] + b_hh[gc0];
    bias1 = b_ih[gc1] + b_hh[gc1];
  }

  // prefetch buf1
  {
    int rbn = yid + 9;
    int rbl = (rbn < 4096) ? rbn : 0;
#pragma unroll
    for (int i = 0; i < 16; ++i) {
      int idx = tid + i * 256;
      int p = idx >> 11, rem = idx & 2047;
      int r = rem >> 5, c = rem & 31;
      const __nv_bfloat16* xp = p ? g_xlo : g_xhi;
      CP_ASYNC16(sbase + PBUF_B + p * 32768 + r * 512 + swz(r, c) * 16,
                 (const char*)xp + ((size_t)(rbl * 64 + r)) * 512 + c * 16);
    }
    CP_COMMIT();
  }

  const int rA = lane & 15, eA = lane >> 4;
  int cur = 0;
#pragma unroll 1
  for (int rb = yid; rb < 4096; rb += 9) {
    CP_WAIT(1);        // current buffer ready
    __syncthreads();
    const uint32_t Abuf = sbase + cur * PBUF_B;
#pragma unroll
    for (int mt = 0; mt < 4; ++mt) {
      float d[4] = {0.f, 0.f, 0.f, 0.f};
      const uint32_t aRow = Abuf + (mt * 16 + rA) * 512;
#pragma unroll
      for (int kp = 0; kp < 8; ++kp) {
        uint32_t h0r, h1r, h2r, h3r, h4, h5, h6, h7;
        uint32_t l0, l1, l2, l3, l4, l5, l6, l7;
        uint32_t a0 = aRow + swz(rA, 4 * kp + eA) * 16;
        uint32_t a1 = aRow + swz(rA, 4 * kp + 2 + eA) * 16;
        LDSM_X4(h0r, h1r, h2r, h3r, a0);
        LDSM_X4(l0, l1, l2, l3, a0 + 32768);
        LDSM_X4(h4, h5, h6, h7, a1);
        LDSM_X4(l4, l5, l6, l7, a1 + 32768);
        MMA_BF16(d, h0r, h1r, h2r, h3r, bH[kp][0], bH[kp][1]);
        MMA_BF16(d, h0r, h1r, h2r, h3r, bL[kp][0], bL[kp][1]);
        MMA_BF16(d, l0, l1, l2, l3,     bH[kp][0], bH[kp][1]);
        MMA_BF16(d, h4, h5, h6, h7,     bH[kp][2], bH[kp][3]);
        MMA_BF16(d, h4, h5, h6, h7,     bL[kp][2], bL[kp][3]);
        MMA_BF16(d, l4, l5, l6, l7,     bH[kp][2], bH[kp][3]);
      }
      size_t row0 = (size_t)rb * 64 + mt * 16 + (lane >> 2);
      float2 s0 = make_float2(d[0] + bias0, d[1] + bias1);
      float2 s1 = make_float2(d[2] + bias0, d[3] + bias1);
      __stcs((float2*)&g_P[row0 * GH_ + ht * 64 + n0], s0);
      __stcs((float2*)&g_P[(row0 + 8) * GH_ + ht * 64 + n0], s1);
    }
    __syncthreads();   // all warps done with cur buffer
    {
      int rb2 = rb + 18;
      int rbl = (rb2 < 4096) ? rb2 : 0;   // dummy tail load keeps invariant
#pragma unroll
      for (int i = 0; i < 16; ++i) {
        int idx = tid + i * 256;
        int p = idx >> 11, rem = idx & 2047;
        int r = rem >> 5, c = rem & 31;
        const __nv_bfloat16* xp = p ? g_xlo : g_xhi;
        CP_ASYNC16(Abuf + p * 32768 + r * 512 + swz(r, c) * 16,
                   (const char*)xp + ((size_t)(rbl * 64 + r)) * 512 + c * 16);
      }
      CP_COMMIT();
    }
    cur ^= 1;
  }
  CP_WAIT(0);          // drain before exit
}

__device__ __forceinline__ void bar_arrive(unsigned* ctr) {
  __syncthreads();
  if (threadIdx.x == 0) {
    asm volatile("red.release.gpu.global.add.u32 [%0], %1;"
                 :: "l"(ctr), "r"(1u) : "memory");
  }
}
__device__ __forceinline__ void bar_wait(unsigned* ctr, unsigned target) {
  if (threadIdx.x == 0) {
    unsigned v;
    do {
      asm volatile("ld.acquire.gpu.b32 %0, [%1];" : "=r"(v) : "l"(ctr) : "memory");
    } while (v < target);
  }
  __syncthreads();
}

// ---------------------------------------------------------------------------
// Persistent recurrent kernel (UNCHANGED from R13): 128 CTAs x 512 threads.
// ---------------------------------------------------------------------------
__global__ void __launch_bounds__(NTHR, 1) lstm_kernel(
    const float* __restrict__ c0,
    const float* __restrict__ w_ih, const float* __restrict__ b_ih,
    const float* __restrict__ w_hh, const float* __restrict__ b_hh,
    float* __restrict__ out) {
  extern __shared__ char smemc[];
  float* sC = (float*)(smemc + OFF_C);
  const uint32_t sbase = s2u(smemc);

  const int tid  = threadIdx.x;
  const int lane = tid & 31;
  const int wid  = tid >> 5;
  const int bt   = blockIdx.x >> 4;
  const int ht   = blockIdx.x & 15;
  const int grp  = wid >> 3;
  const int nsl  = wid & 7;
  unsigned* ctr  = &g_bars[bt][0];

  uint32_t bH[8][4], bL[8][4];
  {
    const int rrow = nsl * 8 + (lane & 7);
    const int bsel = (lane >> 3) & 3;
#pragma unroll 1
    for (int l = 0; l < 2; ++l) {
#pragma unroll 1
      for (int p = 0; p < 2; ++p) {
        for (int idx = tid; idx < 64 * 256; idx += NTHR) {
          int n = idx >> 8, k = idx & 255;
          int g = n & 3, hv = n >> 2;
          int gcol = g * 256 + ht * 16 + hv;
          float v;
          if (l == 0) v = w_hh[(size_t)gcol * H_ + k];
          else v = w_ih[(size_t)(GH_ + gcol) * IN_ + k] +
                   w_hh[(size_t)(GH_ + gcol) * H_ + k];
          __nv_bfloat16 hb = __float2bfloat16(v);
          __nv_bfloat16 sv = p == 0 ? hb
                           : __float2bfloat16(v - __bfloat162float(hb));
          int c = k >> 3;
          *(__nv_bfloat16*)(smemc + OFF_WST + n * 512 + swz(n, c) * 16 +
                            (k & 7) * 2) = sv;
        }
        __syncthreads();
        if (grp == l) {
#pragma unroll
          for (int kp = 0; kp < 8; ++kp) {
            int c = kp * 4 + bsel;
            uint32_t addr = sbase + OFF_WST + rrow * 512 + swz(rrow, c) * 16;
            if (p == 0) { LDSM_X4(bH[kp][0], bH[kp][1], bH[kp][2], bH[kp][3], addr); }
            else        { LDSM_X4(bL[kp][0], bL[kp][1], bL[kp][2], bL[kp][3], addr); }
          }
        }
        __syncthreads();
      }
    }
  }

  const int hv_c   = nsl * 2 + ((lane & 3) >> 1);
  const int bl_c   = (lane >> 2) + ((lane & 1) ? 8 : 0);
  const int bglob  = bt * 16 + bl_c;
  const int hglob  = ht * 16 + hv_c;
  float4 bias4 = make_float4(0.f, 0.f, 0.f, 0.f);
  if (grp == 1) {
#pragma unroll
    for (int g = 0; g < 4; ++g) {
      int gc = g * 256 + ht * 16 + hv_c;
      ((float*)&bias4)[g] = b_ih[GH_ + gc] + b_hh[GH_ + gc];
    }
  }
  if (tid < 256) sC[(tid >> 4) * 17 + (tid & 15)] =
      c0[(size_t)(bt * 16 + (tid >> 4)) * H_ + ht * 16 + (tid & 15)];
  __syncthreads();

  float4 pv = make_float4(0.f, 0.f, 0.f, 0.f);
  if (grp == 0)
    pv = __ldcs((const float4*)&g_P[(size_t)bglob * GH_ + ht * 64 + hv_c * 4]);

  const int rA = lane & 15, eA = lane >> 4;
  const uint32_t aRow = sbase + OFF_A + rA * 512;

#pragma unroll 1
  for (int q = 0; q < 2 * S_; ++q) {
    const int t  = q >> 1;
    const int ph = q & 1;
    if (q) bar_wait(ctr, (unsigned)q * 16);

    {
      int i0 = tid;
#pragma unroll
      for (int ii = 0; ii < 2; ++ii) {
        int idx = i0 + ii * NTHR;
        int p = idx >> 9, rem = idx & 511;
        int r = rem >> 5, c = rem & 31;
        uint32_t dst = sbase + OFF_A + p * 8192 + r * 512 + swz(r, c) * 16;
        const unsigned char* src = &g_img[ph][bt][p][r * 512 + c * 16];
        CP_ASYNC16(dst, src);
      }
      CP_COMMIT();
      CP_WAIT(0);
    }
    __syncthreads();

    if (grp == ph) {
      float d[4] = {0.f, 0.f, 0.f, 0.f};
#pragma unroll
      for (int kp = 0; kp < 8; ++kp) {
        uint32_t h0r, h1r, h2r, h3r, h4, h5, h6, h7;
        uint32_t l0, l1, l2, l3, l4, l5, l6, l7;
        int c0c = 4 * kp + eA;
        int c1c = 4 * kp + 2 + eA;
        uint32_t a0 = aRow + swz(rA, c0c) * 16;
        uint32_t a1 = aRow + swz(rA, c1c) * 16;
        LDSM_X4(h0r, h1r, h2r, h3r, a0);
        LDSM_X4(l0, l1, l2, l3, a0 + 8192);
        LDSM_X4(h4, h5, h6, h7, a1);
        LDSM_X4(l4, l5, l6, l7, a1 + 8192);
        MMA_BF16(d, h0r, h1r, h2r, h3r, bH[kp][0], bH[kp][1]);
        MMA_BF16(d, h0r, h1r, h2r, h3r, bL[kp][0], bL[kp][1]);
        MMA_BF16(d, l0, l1, l2, l3,     bH[kp][0], bH[kp][1]);
        MMA_BF16(d, h4, h5, h6, h7,     bH[kp][2], bH[kp][3]);
        MMA_BF16(d, h4, h5, h6, h7,     bL[kp][2], bL[kp][3]);
        MMA_BF16(d, l4, l5, l6, l7,     bH[kp][2], bH[kp][3]);
      }
      float e0 = __shfl_xor_sync(0xFFFFFFFFu, d[0], 1);
      float e1 = __shfl_xor_sync(0xFFFFFFFFu, d[1], 1);
      float e2 = __shfl_xor_sync(0xFFFFFFFFu, d[2], 1);
      float e3 = __shfl_xor_sync(0xFFFFFFFFu, d[3], 1);
      float gi, gf, gc, go;
      if (!(lane & 1)) { gi = d[0]; gf = d[1]; gc = e0; go = e1; }
      else             { gi = e2;   gf = e3;   gc = d[2]; go = d[3]; }
      float4 ab = (grp == 0) ? pv : bias4;
      gi += ab.x; gf += ab.y; gc += ab.z; go += ab.w;
      int ci = bl_c * 17 + hv_c;
      float cold = sC[ci];
      float cnew = sigf(gf) * cold + sigf(gi) * fmaxf(gc, 0.0f);
      float h = sigf(go) * fmaxf(cnew, 0.0f);
      sC[ci] = cnew;
      __nv_bfloat16 hb = __float2bfloat16(h);
      __nv_bfloat16 lb = __float2bfloat16(h - __bfloat162float(hb));
      *(__nv_bfloat16*)&g_img[ph ^ 1][bt][0][bl_c * 512 + hglob * 2] = hb;
      *(__nv_bfloat16*)&g_img[ph ^ 1][bt][1][bl_c * 512 + hglob * 2] = lb;
      if (t == S_ - 1) {
        size_t lo2 = (size_t)ph * B_ * H_ + (size_t)bglob * H_ + hglob;
        out[HY_OFF + lo2] = h;
        out[CY_OFF + lo2] = cnew;
      }
      bar_arrive(ctr);
      if (ph) __stcs(&out[(size_t)t * B_ * H_ + (size_t)bglob * H_ + hglob], h);
    } else {
      bar_arrive(ctr);
      if (grp == 0 && ph == 1 && t + 1 < S_)
        pv = __ldcs((const float4*)
                    &g_P[((size_t)(t + 1) * B_ + bglob) * GH_ + ht * 64 + hv_c * 4]);
    }
  }
}

extern "C" void kernel_launch(void* const* d_in, const int* in_sizes, int n_in,
                              void* d_out, int out_size) {
  const float* x    = (const float*)d_in[0];
  const float* h0   = (const float*)d_in[1];
  const float* c0   = (const float*)d_in[2];
  const float* w_ih = (const float*)d_in[3];
  const float* b_ih = (const float*)d_in[4];
  const float* w_hh = (const float*)d_in[5];
  const float* b_hh = (const float*)d_in[6];
  float* out = (float*)d_out;

  static bool attr_done = false;
  if (!attr_done) {
    cudaFuncSetAttribute(pro_main,
                         cudaFuncAttributeMaxDynamicSharedMemorySize, PRO_SMEM);
    cudaFuncSetAttribute(lstm_kernel,
                         cudaFuncAttributeMaxDynamicSharedMemorySize, LSTM_SMEM);
    attr_done = true;
  }

  setup_kernel<<<64, 256>>>(h0, w_ih);
  xconv_kernel<<<16384, 512>>>(x);
  pro_main<<<dim3(16, 9), 256, PRO_SMEM>>>(b_ih, b_hh);
  lstm_kernel<<<NCTA, NTHR, LSTM_SMEM>>>(c0, w_ih, b_ih, w_hh, b_hh, out);
}